// round 6
// baseline (speedup 1.0000x reference)
#include <cuda_runtime.h>
#include <cfloat>
#include <math.h>

// Fixed problem shape (setup_inputs): N=8192, IN_F=512, OUT_F=64, C=2, k=32
#define N_     8192
#define INF_   512
#define OUTF_  64
#define C_     2
#define CAP    1024
#define KMAX   64
#define T0     2.2f

// Scratch for h = x @ W^T  [N_, OUTF_]  (2MB, device global: no allocations allowed)
__device__ float g_h[N_ * OUTF_];

__device__ __forceinline__ unsigned long long fma2(unsigned long long a,
                                                   unsigned long long b,
                                                   unsigned long long c) {
    unsigned long long d;
    asm("fma.rn.f32x2 %0, %1, %2, %3;" : "=l"(d) : "l"(a), "l"(b), "l"(c));
    return d;
}
__device__ __forceinline__ unsigned long long pack2(float lo, float hi) {
    unsigned long long d;
    asm("mov.b64 %0, {%1, %2};" : "=l"(d) : "f"(lo), "f"(hi));
    return d;
}

// ---------------------------------------------------------------------------
// Kernel 1: h[n][f] = sum_kk x[n][kk] * W[f][kk]
// Block: 32 rows x 64 f, 256 threads; thread = 4 rows x 2 f (f32x2 packed).
// Lane map: rg = lane&7 (rows), f2 = w*4 + lane>>3 (f-pair) -> per warp only
// 8 distinct x addrs and 4 distinct W row-pairs per load (L1-wavefront-free).
// x staged in smem PRE-DUPLICATED (a,a) so fma2 consumes it directly.
// ---------------------------------------------------------------------------
__global__ void __launch_bounds__(256) h_kernel(const float* __restrict__ x,
                                                const float* __restrict__ W) {
    __shared__ float4 xs[32 * 64];  // 32 rows x 128 kk, duplicated pairs: 32KB
    const int t  = threadIdx.x;
    const int w  = t >> 5;
    const int l  = t & 31;
    const int rg = l & 7;               // row group: rows rg*4 .. rg*4+3
    const int f2 = (w << 2) | (l >> 3); // f-pair 0..31 -> f = 2*f2, 2*f2+1
    const int rowBase = blockIdx.x * 32;
    const float4* x4 = (const float4*)x;  // x row = 128 float4

    unsigned long long acc[4] = {0ull, 0ull, 0ull, 0ull};

    for (int ch = 0; ch < 4; ch++) {
        // stage x chunk [32 rows][128 kk] as duplicated pairs
#pragma unroll
        for (int i = 0; i < 4; i++) {
            int e = t + 256 * i;            // 0..1023
            int rr = e >> 5, cc = e & 31;   // row, kk4 index
            float4 a = x4[(long)(rowBase + rr) * 128 + ch * 32 + cc];
            float4* d = xs + rr * 64 + cc * 2;
            d[0] = make_float4(a.x, a.x, a.y, a.y);
            d[1] = make_float4(a.z, a.z, a.w, a.w);
        }
        __syncthreads();

        const float4* Wf0 = (const float4*)(W + (2 * f2)     * INF_ + ch * 128);
        const float4* Wf1 = (const float4*)(W + (2 * f2 + 1) * INF_ + ch * 128);
#pragma unroll 8
        for (int q = 0; q < 32; q++) {      // kk4 within chunk
            float4 b0 = __ldg(Wf0 + q);
            float4 b1 = __ldg(Wf1 + q);
            unsigned long long p0 = pack2(b0.x, b1.x);
            unsigned long long p1 = pack2(b0.y, b1.y);
            unsigned long long p2 = pack2(b0.z, b1.z);
            unsigned long long p3 = pack2(b0.w, b1.w);
#pragma unroll
            for (int j = 0; j < 4; j++) {
                const ulonglong2* a2 = (const ulonglong2*)(xs + (rg * 4 + j) * 64 + q * 2);
                ulonglong2 u0 = a2[0];   // (a0,a0),(a1,a1)
                ulonglong2 u1 = a2[1];   // (a2,a2),(a3,a3)
                acc[j] = fma2(u0.x, p0, acc[j]);
                acc[j] = fma2(u0.y, p1, acc[j]);
                acc[j] = fma2(u1.x, p2, acc[j]);
                acc[j] = fma2(u1.y, p3, acc[j]);
            }
        }
        __syncthreads();
    }
#pragma unroll
    for (int j = 0; j < 4; j++) {
        float lo = __uint_as_float((unsigned)(acc[j] & 0xffffffffu));
        float hi = __uint_as_float((unsigned)(acc[j] >> 32));
        *(float2*)&g_h[(long)(rowBase + rg * 4 + j) * OUTF_ + 2 * f2] = make_float2(lo, hi);
    }
}

// ---------------------------------------------------------------------------
// Kernel 2: per attention row (16384 blocks)
// ---------------------------------------------------------------------------
__global__ void __launch_bounds__(256) topk_kernel(const float* __restrict__ araw,
                                                   const int*   __restrict__ kptr,
                                                   float*       __restrict__ out,
                                                   float*       __restrict__ att) {
    __shared__ float cval[CAP];
    __shared__ int   cidx[CAP];
    __shared__ int   sidx[KMAX];
    __shared__ float sw[KMAX];
    __shared__ float s_red[8];
    __shared__ float s_bv[8];
    __shared__ int   s_bi[8];
    __shared__ int   s_m;
    __shared__ float s_M;
    __shared__ float s_inv;
    __shared__ float s_lastV;
    __shared__ int   s_lastI;

    const int t    = threadIdx.x;
    const int lane = t & 31;
    const int wid  = t >> 5;
    const long r   = blockIdx.x;

    int k = 32;
    if (kptr) { k = *kptr; if (k < 1) k = 1; if (k > KMAX) k = KMAX; }

    if (t == 0) s_m = 0;
    if (t < KMAX) sw[t] = 0.f;   // zero-pad for fixed-tree reduction

    // ---- front-batched streaming loads (MLP=8) + interleaved zero stores ----
    const float4* src = (const float4*)(araw + r * (long)N_);
    float4 v[8];
#pragma unroll
    for (int i = 0; i < 8; i++) v[i] = __ldcs(src + t + 256 * i);

    if (att) {
        float4* dst = (float4*)(att + r * (long)N_);
        const float4 z = make_float4(0.f, 0.f, 0.f, 0.f);
#pragma unroll
        for (int i = 0; i < 8; i++) __stcs(dst + t + 256 * i, z);
    }
    __syncthreads();   // s_m / sw init visible; cheap (all threads at load-wait)

    // ---- ballot-aggregated candidate extraction ----
#define EXTRACT(val, gidx) do {                                                 \
        unsigned msk_ = __ballot_sync(0xffffffffu, (val) >= T0);                \
        if (msk_) {                                                             \
            int base_;                                                          \
            if (lane == 0) base_ = atomicAdd(&s_m, __popc(msk_));               \
            base_ = __shfl_sync(0xffffffffu, base_, 0);                         \
            if ((val) >= T0) {                                                  \
                int p_ = base_ + __popc(msk_ & ((1u << lane) - 1u));            \
                if (p_ < CAP) { cval[p_] = (val); cidx[p_] = (gidx); }          \
            }                                                                   \
        }                                                                       \
    } while (0)

#pragma unroll
    for (int i = 0; i < 8; i++) {
        int b4 = 4 * (t + 256 * i);
        EXTRACT(v[i].x, b4);
        EXTRACT(v[i].y, b4 + 1);
        EXTRACT(v[i].z, b4 + 2);
        EXTRACT(v[i].w, b4 + 3);
    }
#undef EXTRACT
    __syncthreads();
    const int m = s_m;

    if (m >= k && m <= CAP) {
        // ---- max over candidates (row max is a candidate since m >= k >= 1) ----
        float lm = -FLT_MAX;
        for (int i = t; i < m; i += 256) lm = fmaxf(lm, cval[i]);
#pragma unroll
        for (int o = 16; o > 0; o >>= 1)
            lm = fmaxf(lm, __shfl_xor_sync(0xffffffffu, lm, o));
        if (lane == 0) s_red[wid] = lm;
        __syncthreads();
        if (t == 0) {
            float mm = s_red[0];
#pragma unroll
            for (int j = 1; j < 8; j++) mm = fmaxf(mm, s_red[j]);
            s_M = mm;
        }
        __syncthreads();
        const float M = s_M;

        // ---- exact rank (value desc, index asc — jax tie-break) ----
        for (int i = t; i < m; i += 256) {
            float vi = cval[i];
            int   ii = cidx[i];
            int rank = 0;
            for (int j = 0; j < m; j++) {
                float vj = cval[j];
                rank += (vj > vi) || (vj == vi && cidx[j] < ii);
            }
            if (rank < k) { sidx[rank] = ii; sw[rank] = expf(vi - M); }
        }
        __syncthreads();
    } else {
        // ---- robust fallback: k deterministic arg-max passes over global ----
        if (t == 0) { s_lastV = FLT_MAX; s_lastI = -1; }
        __syncthreads();
        const float* rowg = araw + r * (long)N_;
        for (int p = 0; p < k; p++) {
            float lastV = s_lastV; int lastI = s_lastI;
            float bv = -FLT_MAX; int bi = N_;
            for (int e = t; e < N_; e += 256) {
                float vv = rowg[e];
                bool after = (vv < lastV) || (vv == lastV && e > lastI);
                if (after && ((vv > bv) || (vv == bv && e < bi))) { bv = vv; bi = e; }
            }
#pragma unroll
            for (int o = 16; o > 0; o >>= 1) {
                float ov = __shfl_xor_sync(0xffffffffu, bv, o);
                int   oi = __shfl_xor_sync(0xffffffffu, bi, o);
                if ((ov > bv) || (ov == bv && oi < bi)) { bv = ov; bi = oi; }
            }
            if (lane == 0) { s_bv[wid] = bv; s_bi[wid] = bi; }
            __syncthreads();
            if (t == 0) {
                float gv = s_bv[0]; int gi = s_bi[0];
#pragma unroll
                for (int j = 1; j < 8; j++) {
                    if ((s_bv[j] > gv) || (s_bv[j] == gv && s_bi[j] < gi)) { gv = s_bv[j]; gi = s_bi[j]; }
                }
                if (p == 0) s_M = gv;
                sidx[p] = gi; sw[p] = expf(gv - s_M);
                s_lastV = gv; s_lastI = gi;
            }
            __syncthreads();
        }
    }

    // ---- deterministic softmax denominator: fixed warp-0 shuffle tree ----
    if (wid == 0) {
        float s = sw[lane] + sw[lane + 32];   // KMAX=64, zero-padded
#pragma unroll
        for (int o = 16; o > 0; o >>= 1)
            s += __shfl_xor_sync(0xffffffffu, s, o);
        if (lane == 0) s_inv = 1.0f / s;
    }
    __syncthreads();
    const float inv = s_inv;

    // ---- scatter the k softmax values (zeros already streamed out) ----
    if (att && t < k) att[r * (long)N_ + sidx[t]] = sw[t] * inv;

    // ---- h_prime row -> concat-transposed output [n, c*OUTF + f] ----
    if (out && t < OUTF_) {
        float acc = 0.f;
        for (int p = 0; p < k; p++)
            acc = fmaf(sw[p] * inv, g_h[sidx[p] * OUTF_ + t], acc);
        const int c = (int)(r / N_);
        const int n = (int)(r % N_);
        out[(long)n * (C_ * OUTF_) + c * OUTF_ + t] = acc;
    }
}

// ---------------------------------------------------------------------------
extern "C" void kernel_launch(void* const* d_in, const int* in_sizes, int n_in,
                              void* d_out, int out_size) {
    const float* x    = (const float*)d_in[0];
    const float* W    = (const float*)d_in[1];
    const float* araw = (const float*)d_in[2];
    const int*   kptr = (n_in > 3) ? (const int*)d_in[3] : nullptr;

    const long attElems = (long)in_sizes[2];        // R * N
    const int  R        = (int)(attElems / N_);     // 16384
    const long outElems = (long)N_ * C_ * OUTF_;    // 1,048,576

    float* outp = nullptr;
    float* attp = nullptr;
    const long osz = (long)out_size;
    if (osz >= outElems + attElems) {
        outp = (float*)d_out;
        attp = (float*)d_out + outElems;   // tuple order: (out, att)
    } else if (osz == attElems) {
        attp = (float*)d_out;
    } else {
        outp = (float*)d_out;
    }

    if (outp) h_kernel<<<N_ / 32, 256>>>(x, W);
    topk_kernel<<<R, 256>>>(araw, kptr, outp, attp);
}

// round 8
// speedup vs baseline: 1.7954x; 1.7954x over previous
#include <cuda_runtime.h>
#include <cfloat>
#include <math.h>

// Fixed problem shape (setup_inputs): N=8192, IN_F=512, OUT_F=64, C=2, k=32
#define N_     8192
#define INF_   512
#define OUTF_  64
#define C_     2
#define RMAX   16384
#define CAP2   320
#define KMAX   64
#define T0     2.2f

// Static device scratch (no allocations allowed)
__device__ float  g_h[N_ * OUTF_];              // 2MB   h = x @ W^T
__device__ float2 g_cand[(long)RMAX * CAP2];    // 40MB  (val, idx) per row
__device__ int    g_cnt[RMAX];

// ---------------------------------------------------------------------------
// Kernel 1: h = x @ W^T. Tiled GEMM: block = 64 rows x 64 f, 256 threads,
// thread tile 4x4. W smem stride 65 (pad) + f = tx+16*i => conflict-free LDS.
// ---------------------------------------------------------------------------
__global__ void __launch_bounds__(256) h_kernel(const float* __restrict__ x,
                                                const float* __restrict__ W) {
    __shared__ float x_s[64 * 64];   // [row][kk]   16KB
    __shared__ float w_s[64 * 65];   // [f][kk] pad 16.25KB
    const int t  = threadIdx.x;
    const int tx = t & 15;           // f lane: f = tx + 16*i
    const int ty = t >> 4;           // rows ty*4 .. ty*4+3
    const int rowBase = blockIdx.x * 64;

    const float4* x4 = (const float4*)x;   // row = 128 float4
    const float4* W4 = (const float4*)W;

    float acc[4][4];
#pragma unroll
    for (int j = 0; j < 4; j++)
#pragma unroll
        for (int i = 0; i < 4; i++) acc[j][i] = 0.f;

    for (int ch = 0; ch < 8; ch++) {   // 64-kk chunks
        // stage x [64 rows][64 kk] and W [64 f][64 kk], both coalesced
#pragma unroll
        for (int i = 0; i < 4; i++) {
            int idx = t + 256 * i;         // 0..1023
            int rr = idx >> 4, c4 = idx & 15;
            float4 a = x4[(long)(rowBase + rr) * 128 + ch * 16 + c4];
            *(float4*)&x_s[rr * 64 + c4 * 4] = a;
            float4 b = W4[(long)rr * 128 + ch * 16 + c4];  // rr = f here
            float* d = &w_s[rr * 65 + c4 * 4];
            d[0] = b.x; d[1] = b.y; d[2] = b.z; d[3] = b.w;
        }
        __syncthreads();

#pragma unroll 4
        for (int kk = 0; kk < 64; kk++) {
            float xv[4], wv[4];
#pragma unroll
            for (int j = 0; j < 4; j++) xv[j] = x_s[(ty * 4 + j) * 64 + kk];
#pragma unroll
            for (int i = 0; i < 4; i++) wv[i] = w_s[(tx + 16 * i) * 65 + kk];
#pragma unroll
            for (int j = 0; j < 4; j++)
#pragma unroll
                for (int i = 0; i < 4; i++)
                    acc[j][i] = fmaf(xv[j], wv[i], acc[j][i]);
        }
        __syncthreads();
    }
#pragma unroll
    for (int j = 0; j < 4; j++)
#pragma unroll
        for (int i = 0; i < 4; i++)
            g_h[(long)(rowBase + ty * 4 + j) * OUTF_ + tx + 16 * i] = acc[j][i];
}

// ---------------------------------------------------------------------------
// Kernel 2 (stream): per row — read once, zero att, extract candidates >= T0
// into global scratch. Minimal ALU, minimal registers, no rank logic.
// ---------------------------------------------------------------------------
__global__ void __launch_bounds__(256) stream_kernel(const float* __restrict__ araw,
                                                     float* __restrict__ att) {
    __shared__ int s_m;
    const int t  = threadIdx.x;
    const long r = blockIdx.x;
    if (t == 0) s_m = 0;
    __syncthreads();

    const float4* src = (const float4*)(araw + r * (long)N_);
    float4* dst = att ? (float4*)(att + r * (long)N_) : nullptr;
    float2* cb = g_cand + r * CAP2;
    const float4 z = make_float4(0.f, 0.f, 0.f, 0.f);

#pragma unroll
    for (int i = 0; i < 8; i++) {
        int e4 = t + 256 * i;
        float4 v = __ldcs(src + e4);
        if (dst) __stcs(dst + e4, z);
        int b4 = 4 * e4;
        if (v.x >= T0) { int p = atomicAdd(&s_m, 1); if (p < CAP2) cb[p] = make_float2(v.x, __int_as_float(b4));     }
        if (v.y >= T0) { int p = atomicAdd(&s_m, 1); if (p < CAP2) cb[p] = make_float2(v.y, __int_as_float(b4 + 1)); }
        if (v.z >= T0) { int p = atomicAdd(&s_m, 1); if (p < CAP2) cb[p] = make_float2(v.z, __int_as_float(b4 + 2)); }
        if (v.w >= T0) { int p = atomicAdd(&s_m, 1); if (p < CAP2) cb[p] = make_float2(v.w, __int_as_float(b4 + 3)); }
    }
    __syncthreads();
    if (t == 0) g_cnt[r] = s_m;
}

// ---------------------------------------------------------------------------
// Kernel 3 (rank): per row, 128 threads. Exact top-k over candidates
// (jax tie-break), softmax, scatter att values, gather h' into output.
// ---------------------------------------------------------------------------
__global__ void __launch_bounds__(128) rank_kernel(const float* __restrict__ araw,
                                                   const int*   __restrict__ kptr,
                                                   float*       __restrict__ out,
                                                   float*       __restrict__ att) {
    __shared__ float cval[CAP2];
    __shared__ int   cidx[CAP2];
    __shared__ int   sidx[KMAX];
    __shared__ float sw[KMAX];
    __shared__ float s_red[4];
    __shared__ float s_bv[4];
    __shared__ int   s_bi[4];
    __shared__ float s_M;
    __shared__ float s_inv;
    __shared__ float s_lastV;
    __shared__ int   s_lastI;

    const int t    = threadIdx.x;
    const int lane = t & 31;
    const int wid  = t >> 5;
    const long r   = blockIdx.x;

    int k = 32;
    if (kptr) { k = *kptr; if (k < 1) k = 1; if (k > KMAX) k = KMAX; }

    if (t < KMAX) sw[t] = 0.f;   // zero-pad for fixed-tree sum
    const int m = g_cnt[r];

    if (m >= k && m <= CAP2) {
        const float2* cb = g_cand + r * CAP2;
        for (int i = t; i < m; i += 128) {
            float2 c = cb[i];
            cval[i] = c.x;
            cidx[i] = __float_as_int(c.y);
        }
        __syncthreads();

        // max over candidates (row max is among them since m >= k >= 1)
        float lm = -FLT_MAX;
        for (int i = t; i < m; i += 128) lm = fmaxf(lm, cval[i]);
#pragma unroll
        for (int o = 16; o > 0; o >>= 1)
            lm = fmaxf(lm, __shfl_xor_sync(0xffffffffu, lm, o));
        if (lane == 0) s_red[wid] = lm;
        __syncthreads();
        if (t == 0)
            s_M = fmaxf(fmaxf(s_red[0], s_red[1]), fmaxf(s_red[2], s_red[3]));
        __syncthreads();
        const float M = s_M;

        // exact rank: value desc, index asc
        for (int i = t; i < m; i += 128) {
            float vi = cval[i];
            int   ii = cidx[i];
            int rank = 0;
            for (int j = 0; j < m; j++) {
                float vj = cval[j];
                rank += (vj > vi) || (vj == vi && cidx[j] < ii);
            }
            if (rank < k) { sidx[rank] = ii; sw[rank] = expf(vi - M); }
        }
        __syncthreads();
    } else {
        // robust fallback: k deterministic arg-max passes over the global row
        if (t == 0) { s_lastV = FLT_MAX; s_lastI = -1; }
        __syncthreads();
        const float* rowg = araw + r * (long)N_;
        for (int p = 0; p < k; p++) {
            float lastV = s_lastV; int lastI = s_lastI;
            float bv = -FLT_MAX; int bi = N_;
            for (int e = t; e < N_; e += 128) {
                float vv = rowg[e];
                bool after = (vv < lastV) || (vv == lastV && e > lastI);
                if (after && ((vv > bv) || (vv == bv && e < bi))) { bv = vv; bi = e; }
            }
#pragma unroll
            for (int o = 16; o > 0; o >>= 1) {
                float ov = __shfl_xor_sync(0xffffffffu, bv, o);
                int   oi = __shfl_xor_sync(0xffffffffu, bi, o);
                if ((ov > bv) || (ov == bv && oi < bi)) { bv = ov; bi = oi; }
            }
            if (lane == 0) { s_bv[wid] = bv; s_bi[wid] = bi; }
            __syncthreads();
            if (t == 0) {
                float gv = s_bv[0]; int gi = s_bi[0];
#pragma unroll
                for (int j = 1; j < 4; j++) {
                    if ((s_bv[j] > gv) || (s_bv[j] == gv && s_bi[j] < gi)) { gv = s_bv[j]; gi = s_bi[j]; }
                }
                if (p == 0) s_M = gv;
                sidx[p] = gi; sw[p] = expf(gv - s_M);
                s_lastV = gv; s_lastI = gi;
            }
            __syncthreads();
        }
    }

    // deterministic softmax denominator: fixed warp-0 shuffle tree
    if (wid == 0) {
        float s = sw[lane] + sw[lane + 32];
#pragma unroll
        for (int o = 16; o > 0; o >>= 1)
            s += __shfl_xor_sync(0xffffffffu, s, o);
        if (lane == 0) s_inv = 1.0f / s;
    }
    __syncthreads();
    const float inv = s_inv;

    // scatter k softmax values (zeros already written by stream_kernel)
    if (att && t < k) att[r * (long)N_ + sidx[t]] = sw[t] * inv;

    // h_prime row -> concat-transposed output [n, c*OUTF + f]
    if (out && t < OUTF_) {
        float acc = 0.f;
        for (int p = 0; p < k; p++)
            acc = fmaf(sw[p] * inv, g_h[(long)sidx[p] * OUTF_ + t], acc);
        const int c = (int)(r / N_);
        const int n = (int)(r % N_);
        out[(long)n * (C_ * OUTF_) + c * OUTF_ + t] = acc;
    }
}

// ---------------------------------------------------------------------------
extern "C" void kernel_launch(void* const* d_in, const int* in_sizes, int n_in,
                              void* d_out, int out_size) {
    const float* x    = (const float*)d_in[0];
    const float* W    = (const float*)d_in[1];
    const float* araw = (const float*)d_in[2];
    const int*   kptr = (n_in > 3) ? (const int*)d_in[3] : nullptr;

    const long attElems = (long)in_sizes[2];        // R * N
    const int  R        = (int)(attElems / N_);     // 16384
    const long outElems = (long)N_ * C_ * OUTF_;    // 1,048,576

    float* outp = nullptr;
    float* attp = nullptr;
    const long osz = (long)out_size;
    if (osz >= outElems + attElems) {
        outp = (float*)d_out;
        attp = (float*)d_out + outElems;   // tuple order: (out, att)
    } else if (osz == attElems) {
        attp = (float*)d_out;
    } else {
        outp = (float*)d_out;
    }

    if (outp) h_kernel<<<N_ / 64, 256>>>(x, W);
    stream_kernel<<<R, 256>>>(araw, attp);
    rank_kernel<<<R, 128>>>(araw, kptr, outp, attp);
}